// round 14
// baseline (speedup 1.0000x reference)
#include <cuda_runtime.h>

#define BB     32
#define SS     512
#define HH     768
#define NC     32
#define MHL    16
#define H4     (HH / 4)       // 192 float4 per row
#define CPL    6              // float4 chunks per lane
#define TPB    256            // 8 warps
#define GRID   592            // 4 CTAs/SM * 148 SMs, one exact wave
#define NWARPS (GRID * (TPB / 32))   // 4736
#define NROWS  (BB * SS)      // 16384
#define NCOMB  (2 * 11 * 6)   // 132

__device__ float4 g_comb[NCOMB * H4];

__global__ __launch_bounds__(192)
void build_comb_kernel(const float4* __restrict__ tok_type_emb,
                       const float4* __restrict__ match_emb,
                       const float4* __restrict__ type_emb)
{
    const int combo = blockIdx.x;          // 0..131
    const int tt  = combo / 66;
    const int rem = combo % 66;
    const int mt  = rem / 6;
    const int ty  = rem % 6;
    const int tid = threadIdx.x;

    const float4 a = tok_type_emb[tt * H4 + tid];
    const float4 b = match_emb[mt * H4 + tid];
    const float4 c = type_emb[ty * H4 + tid];
    float4 r;
    r.x = a.x + b.x + c.x;
    r.y = a.y + b.y + c.y;
    r.z = a.z + b.z + c.z;
    r.w = a.w + b.w + c.w;
    g_comb[combo * H4 + tid] = r;
}

__global__ __launch_bounds__(TPB, 4)
void bert_emb_kernel(
    const int*    __restrict__ input_ids,       // [B,S]
    const int*    __restrict__ header_ids,      // [B,NC,MHL]
    const int*    __restrict__ token_type_ids,  // [B,S]
    const int*    __restrict__ match_type_ids,  // [B,S]
    const int*    __restrict__ type_idx,        // [B,S]
    const int*    __restrict__ col_pos,         // [B,NC]
    const int*    __restrict__ col_idx,         // [B,NC]
    const int*    __restrict__ header_len,      // [B,NC]
    const float4* __restrict__ word_emb,        // [VOCAB,H4]
    const float4* __restrict__ pos_emb,         // [MAX_POS,H4]
    const float4* __restrict__ ln_w,            // [H4]
    const float4* __restrict__ ln_b,            // [H4]
    float4*       __restrict__ out)             // [B,S,H4]
{
    const int tid  = threadIdx.x;
    const int warp = tid >> 5;
    const int lane = tid & 31;

    __shared__ float4 sgw[H4];
    __shared__ float4 sgb[H4];
    if (tid < H4) {
        sgw[tid] = ln_w[tid];
        sgb[tid] = ln_b[tid];
    }
    __syncthreads();

    // balanced contiguous chunk for this warp: 3 or 4 rows
    const int g      = blockIdx.x * (TPB / 32) + warp;
    const int rstart = (int)(((long long)g * NROWS) / NWARPS);
    const int rend   = (int)(((long long)(g + 1) * NROWS) / NWARPS);

    // hoisted per-batch metadata (reloaded only when the chunk crosses a batch)
    int bcur = rstart >> 9;
    int cp = col_pos[bcur * NC + lane];
    int ci = col_idx[bcur * NC + lane];
    int hl = header_len[bcur * NC + lane];

    #pragma unroll 1
    for (int row = rstart; row < rend; ++row) {
        const int b = row >> 9;
        const int s = row & (SS - 1);

        if (b != bcur) {                     // rare: chunk crosses batch boundary
            bcur = b;
            cp = col_pos[b * NC + lane];
            ci = col_idx[b * NC + lane];
            hl = header_len[b * NC + lane];
        }

        // ---- column-scatter detection (register-only) ----
        const unsigned mm = __ballot_sync(0xffffffffu, cp == s);
        int len = 0, cidx = 0;
        if (mm) {
            const int c = __ffs(mm) - 1;
            cidx = __shfl_sync(0xffffffffu, ci, c);
            len  = __shfl_sync(0xffffffffu, hl, cidx);
        }

        // ---- base vector: word embedding (common) or pooled header (rare) ----
        float4 v[CPL];
        if (len == 0) {
            const size_t base = (size_t)input_ids[row] * H4 + lane;
            #pragma unroll
            for (int k = 0; k < CPL; ++k) v[k] = word_emb[base + k * 32];
        } else {
            #pragma unroll
            for (int k = 0; k < CPL; ++k) v[k] = make_float4(0.f, 0.f, 0.f, 0.f);
            const int* hids = header_ids + (b * NC + cidx) * MHL;
            for (int l = 0; l < len; ++l) {
                const size_t base = (size_t)hids[l] * H4 + lane;
                #pragma unroll
                for (int k = 0; k < CPL; ++k) {
                    const float4 w = word_emb[base + k * 32];
                    v[k].x += w.x; v[k].y += w.y; v[k].z += w.z; v[k].w += w.w;
                }
            }
            const float inv = 1.0f / (float)len;
            #pragma unroll
            for (int k = 0; k < CPL; ++k) {
                v[k].x *= inv; v[k].y *= inv; v[k].z *= inv; v[k].w *= inv;
            }
        }

        // ---- add positional + combined small-table (limited unroll: cap temps) ----
        const int combo = token_type_ids[row] * 66
                        + match_type_ids[row] * 6
                        + type_idx[row];
        const size_t pbase = (size_t)s * H4 + lane;
        const size_t cbase = (size_t)combo * H4 + lane;
        #pragma unroll 3
        for (int k = 0; k < CPL; ++k) {
            const float4 pe = pos_emb[pbase + k * 32];
            const float4 cb = g_comb[cbase + k * 32];
            v[k].x += pe.x + cb.x;
            v[k].y += pe.y + cb.y;
            v[k].z += pe.z + cb.z;
            v[k].w += pe.w + cb.w;
        }

        // ---- LayerNorm: warp butterfly reduce (dual interleaved chains) ----
        float sum = 0.f, sq = 0.f;
        #pragma unroll
        for (int k = 0; k < CPL; ++k) {
            sum += v[k].x + v[k].y + v[k].z + v[k].w;
            sq  += v[k].x * v[k].x + v[k].y * v[k].y
                 + v[k].z * v[k].z + v[k].w * v[k].w;
        }
        #pragma unroll
        for (int o = 16; o > 0; o >>= 1) {
            sum += __shfl_xor_sync(0xffffffffu, sum, o);
            sq  += __shfl_xor_sync(0xffffffffu, sq,  o);
        }
        const float mean = sum * (1.0f / HH);
        float var = fmaxf(sq * (1.0f / HH) - mean * mean, 0.0f);
        const float rstd = rsqrtf(var + 1e-12f);

        // ---- scale, shift, store ----
        float4* orow = out + (size_t)row * H4 + lane;
        #pragma unroll 3
        for (int k = 0; k < CPL; ++k) {
            const float4 gwv = sgw[lane + k * 32];
            const float4 gbv = sgb[lane + k * 32];
            float4 o;
            o.x = (v[k].x - mean) * rstd * gwv.x + gbv.x;
            o.y = (v[k].y - mean) * rstd * gwv.y + gbv.y;
            o.z = (v[k].z - mean) * rstd * gwv.z + gbv.z;
            o.w = (v[k].w - mean) * rstd * gwv.w + gbv.w;
            __stcs(orow + k * 32, o);
        }
    }
}

extern "C" void kernel_launch(void* const* d_in, const int* in_sizes, int n_in,
                              void* d_out, int out_size) {
    (void)in_sizes; (void)n_in; (void)out_size;
    const int*    input_ids       = (const int*)   d_in[0];
    const int*    header_ids      = (const int*)   d_in[1];
    const int*    token_type_ids  = (const int*)   d_in[2];
    const int*    match_type_ids  = (const int*)   d_in[3];
    const int*    type_idx        = (const int*)   d_in[4];
    const int*    col_pos         = (const int*)   d_in[5];
    const int*    col_idx         = (const int*)   d_in[6];
    const int*    header_len      = (const int*)   d_in[7];
    const float4* word_emb        = (const float4*)d_in[8];
    const float4* pos_emb         = (const float4*)d_in[9];
    const float4* tok_type_emb    = (const float4*)d_in[10];
    const float4* match_emb       = (const float4*)d_in[11];
    const float4* type_emb        = (const float4*)d_in[12];
    const float4* ln_w            = (const float4*)d_in[13];
    const float4* ln_b            = (const float4*)d_in[14];
    float4*       out             = (float4*)d_out;

    build_comb_kernel<<<NCOMB, 192>>>(tok_type_emb, match_emb, type_emb);

    bert_emb_kernel<<<GRID, TPB>>>(
        input_ids, header_ids, token_type_ids, match_type_ids, type_idx,
        col_pos, col_idx, header_len, word_emb, pos_emb, ln_w, ln_b, out);
}

// round 15
// speedup vs baseline: 1.0621x; 1.0621x over previous
#include <cuda_runtime.h>

#define BB     32
#define SS     512
#define HH     768
#define NC     32
#define MHL    16
#define H4     (HH / 4)       // 192 float4 per row
#define CPL    6              // float4 chunks per lane
#define TPB    256            // 8 warps
#define GRID   592            // 4 CTAs/SM * 148 SMs, one exact wave
#define NWARPS (GRID * (TPB / 32))   // 4736
#define NROWS  (BB * SS)      // 16384
#define NCOMB  (2 * 11 * 6)   // 132

__device__ float4 g_comb[NCOMB * H4];

__global__ __launch_bounds__(192)
void build_comb_kernel(const float4* __restrict__ tok_type_emb,
                       const float4* __restrict__ match_emb,
                       const float4* __restrict__ type_emb)
{
    const int combo = blockIdx.x;          // 0..131
    const int tt  = combo / 66;
    const int rem = combo % 66;
    const int mt  = rem / 6;
    const int ty  = rem % 6;
    const int tid = threadIdx.x;

    const float4 a = tok_type_emb[tt * H4 + tid];
    const float4 b = match_emb[mt * H4 + tid];
    const float4 c = type_emb[ty * H4 + tid];
    float4 r;
    r.x = a.x + b.x + c.x;
    r.y = a.y + b.y + c.y;
    r.z = a.z + b.z + c.z;
    r.w = a.w + b.w + c.w;
    g_comb[combo * H4 + tid] = r;
}

// ---------------------------------------------------------------------------
// Main kernel: branch-free, every row treated as a plain word-embedding row.
// Scatter-target rows are later overwritten by fix_kernel.
// ---------------------------------------------------------------------------
__global__ __launch_bounds__(TPB, 4)
void bert_emb_main(
    const int*    __restrict__ input_ids,       // [B,S]
    const int*    __restrict__ token_type_ids,  // [B,S]
    const int*    __restrict__ match_type_ids,  // [B,S]
    const int*    __restrict__ type_idx,        // [B,S]
    const float4* __restrict__ word_emb,        // [VOCAB,H4]
    const float4* __restrict__ pos_emb,         // [MAX_POS,H4]
    const float4* __restrict__ ln_w,            // [H4]
    const float4* __restrict__ ln_b,            // [H4]
    float4*       __restrict__ out)             // [B,S,H4]
{
    const int tid  = threadIdx.x;
    const int warp = tid >> 5;
    const int lane = tid & 31;

    __shared__ float4 sgw[H4];
    __shared__ float4 sgb[H4];
    if (tid < H4) {
        sgw[tid] = ln_w[tid];
        sgb[tid] = ln_b[tid];
    }
    __syncthreads();

    // balanced contiguous chunk for this warp: 3 or 4 rows
    const int g      = blockIdx.x * (TPB / 32) + warp;
    const int rstart = (int)(((long long)g * NROWS) / NWARPS);
    const int rend   = (int)(((long long)(g + 1) * NROWS) / NWARPS);

    #pragma unroll 1
    for (int row = rstart; row < rend; ++row) {
        const int s = row & (SS - 1);

        // independent scalar loads: word id + combo index
        const int wid   = input_ids[row];
        const int combo = token_type_ids[row] * 66
                        + match_type_ids[row] * 6
                        + type_idx[row];

        const size_t wbase = (size_t)wid * H4 + lane;
        const size_t pbase = (size_t)s * H4 + lane;
        const size_t cbase = (size_t)combo * H4 + lane;

        float4 v[CPL];
        #pragma unroll
        for (int k = 0; k < CPL; ++k) v[k] = word_emb[wbase + k * 32];
        #pragma unroll
        for (int k = 0; k < CPL; ++k) {
            const float4 pe = pos_emb[pbase + k * 32];
            const float4 cb = g_comb[cbase + k * 32];
            v[k].x += pe.x + cb.x;
            v[k].y += pe.y + cb.y;
            v[k].z += pe.z + cb.z;
            v[k].w += pe.w + cb.w;
        }

        // LayerNorm: warp butterfly reduce (dual interleaved chains)
        float sum = 0.f, sq = 0.f;
        #pragma unroll
        for (int k = 0; k < CPL; ++k) {
            sum += v[k].x + v[k].y + v[k].z + v[k].w;
            sq  += v[k].x * v[k].x + v[k].y * v[k].y
                 + v[k].z * v[k].z + v[k].w * v[k].w;
        }
        #pragma unroll
        for (int o = 16; o > 0; o >>= 1) {
            sum += __shfl_xor_sync(0xffffffffu, sum, o);
            sq  += __shfl_xor_sync(0xffffffffu, sq,  o);
        }
        const float mean = sum * (1.0f / HH);
        float var = fmaxf(sq * (1.0f / HH) - mean * mean, 0.0f);
        const float rstd = rsqrtf(var + 1e-12f);

        float4* orow = out + (size_t)row * H4 + lane;
        #pragma unroll
        for (int k = 0; k < CPL; ++k) {
            const float4 gwv = sgw[lane + k * 32];
            const float4 gbv = sgb[lane + k * 32];
            float4 o;
            o.x = (v[k].x - mean) * rstd * gwv.x + gbv.x;
            o.y = (v[k].y - mean) * rstd * gwv.y + gbv.y;
            o.z = (v[k].z - mean) * rstd * gwv.z + gbv.z;
            o.w = (v[k].w - mean) * rstd * gwv.w + gbv.w;
            __stcs(orow + k * 32, o);
        }
    }
}

// ---------------------------------------------------------------------------
// Fixup kernel: one warp per (b,c); rows with header_len>0 are recomputed
// from the pooled header embedding and overwritten.
// ---------------------------------------------------------------------------
__global__ __launch_bounds__(TPB)
void bert_emb_fix(
    const int*    __restrict__ header_ids,      // [B,NC,MHL]
    const int*    __restrict__ token_type_ids,  // [B,S]
    const int*    __restrict__ match_type_ids,  // [B,S]
    const int*    __restrict__ type_idx,        // [B,S]
    const int*    __restrict__ col_pos,         // [B,NC]
    const int*    __restrict__ col_idx,         // [B,NC]
    const int*    __restrict__ header_len,      // [B,NC]
    const float4* __restrict__ word_emb,        // [VOCAB,H4]
    const float4* __restrict__ pos_emb,         // [MAX_POS,H4]
    const float4* __restrict__ ln_w,            // [H4]
    const float4* __restrict__ ln_b,            // [H4]
    float4*       __restrict__ out)             // [B,S,H4]
{
    const int warp = threadIdx.x >> 5;
    const int lane = threadIdx.x & 31;
    const int gw   = blockIdx.x * (TPB / 32) + warp;   // 0 .. B*NC-1
    const int b    = gw >> 5;                          // gw / NC
    const int c    = gw & (NC - 1);                    // gw % NC

    const int cidx = col_idx[b * NC + c];
    const int len  = header_len[b * NC + cidx];
    if (len == 0) return;

    const int s   = col_pos[b * NC + c];
    const int row = b * SS + s;

    // pooled mean over header tokens
    float4 v[CPL];
    #pragma unroll
    for (int k = 0; k < CPL; ++k) v[k] = make_float4(0.f, 0.f, 0.f, 0.f);
    const int* hids = header_ids + (b * NC + cidx) * MHL;
    for (int l = 0; l < len; ++l) {
        const size_t base = (size_t)hids[l] * H4 + lane;
        #pragma unroll
        for (int k = 0; k < CPL; ++k) {
            const float4 w = word_emb[base + k * 32];
            v[k].x += w.x; v[k].y += w.y; v[k].z += w.z; v[k].w += w.w;
        }
    }
    const float inv = 1.0f / (float)len;

    const int combo = token_type_ids[row] * 66
                    + match_type_ids[row] * 6
                    + type_idx[row];
    const size_t pbase = (size_t)s * H4 + lane;
    const size_t cbase = (size_t)combo * H4 + lane;
    #pragma unroll
    for (int k = 0; k < CPL; ++k) {
        const float4 pe = pos_emb[pbase + k * 32];
        const float4 cb = g_comb[cbase + k * 32];
        v[k].x = v[k].x * inv + pe.x + cb.x;
        v[k].y = v[k].y * inv + pe.y + cb.y;
        v[k].z = v[k].z * inv + pe.z + cb.z;
        v[k].w = v[k].w * inv + pe.w + cb.w;
    }

    float sum = 0.f, sq = 0.f;
    #pragma unroll
    for (int k = 0; k < CPL; ++k) {
        sum += v[k].x + v[k].y + v[k].z + v[k].w;
        sq  += v[k].x * v[k].x + v[k].y * v[k].y
             + v[k].z * v[k].z + v[k].w * v[k].w;
    }
    #pragma unroll
    for (int o = 16; o > 0; o >>= 1) {
        sum += __shfl_xor_sync(0xffffffffu, sum, o);
        sq  += __shfl_xor_sync(0xffffffffu, sq,  o);
    }
    const float mean = sum * (1.0f / HH);
    float var = fmaxf(sq * (1.0f / HH) - mean * mean, 0.0f);
    const float rstd = rsqrtf(var + 1e-12f);

    float4* orow = out + (size_t)row * H4 + lane;
    #pragma unroll
    for (int k = 0; k < CPL; ++k) {
        const float4 gwv = ln_w[lane + k * 32];
        const float4 gbv = ln_b[lane + k * 32];
        float4 o;
        o.x = (v[k].x - mean) * rstd * gwv.x + gbv.x;
        o.y = (v[k].y - mean) * rstd * gwv.y + gbv.y;
        o.z = (v[k].z - mean) * rstd * gwv.z + gbv.z;
        o.w = (v[k].w - mean) * rstd * gwv.w + gbv.w;
        orow[k * 32] = o;
    }
}

extern "C" void kernel_launch(void* const* d_in, const int* in_sizes, int n_in,
                              void* d_out, int out_size) {
    (void)in_sizes; (void)n_in; (void)out_size;
    const int*    input_ids       = (const int*)   d_in[0];
    const int*    header_ids      = (const int*)   d_in[1];
    const int*    token_type_ids  = (const int*)   d_in[2];
    const int*    match_type_ids  = (const int*)   d_in[3];
    const int*    type_idx        = (const int*)   d_in[4];
    const int*    col_pos         = (const int*)   d_in[5];
    const int*    col_idx         = (const int*)   d_in[6];
    const int*    header_len      = (const int*)   d_in[7];
    const float4* word_emb        = (const float4*)d_in[8];
    const float4* pos_emb         = (const float4*)d_in[9];
    const float4* tok_type_emb    = (const float4*)d_in[10];
    const float4* match_emb       = (const float4*)d_in[11];
    const float4* type_emb        = (const float4*)d_in[12];
    const float4* ln_w            = (const float4*)d_in[13];
    const float4* ln_b            = (const float4*)d_in[14];
    float4*       out             = (float4*)d_out;

    build_comb_kernel<<<NCOMB, 192>>>(tok_type_emb, match_emb, type_emb);

    bert_emb_main<<<GRID, TPB>>>(
        input_ids, token_type_ids, match_type_ids, type_idx,
        word_emb, pos_emb, ln_w, ln_b, out);

    // 1024 (b,c) pairs, one warp each -> 128 CTAs of 8 warps
    bert_emb_fix<<<(BB * NC) / (TPB / 32), TPB>>>(
        header_ids, token_type_ids, match_type_ids, type_idx,
        col_pos, col_idx, header_len, word_emb, pos_emb, ln_w, ln_b, out);
}

// round 16
// speedup vs baseline: 1.2991x; 1.2231x over previous
#include <cuda_runtime.h>

#define BB   32
#define SS   512
#define HH   768
#define NC   32
#define MHL  16
#define H4   (HH / 4)       // 192 float4 per row
#define CPL  6              // float4 chunks per lane (192/32)
#define TPB  256            // 8 warps
#define RPW  8              // rows per warp

__global__ __launch_bounds__(TPB, 2)
void bert_emb_kernel(
    const int*    __restrict__ input_ids,       // [B,S]
    const int*    __restrict__ header_ids,      // [B,NC,MHL]
    const int*    __restrict__ token_type_ids,  // [B,S]
    const int*    __restrict__ match_type_ids,  // [B,S]
    const int*    __restrict__ type_idx,        // [B,S]
    const int*    __restrict__ col_pos,         // [B,NC]
    const int*    __restrict__ col_idx,         // [B,NC]
    const int*    __restrict__ header_len,      // [B,NC]
    const float4* __restrict__ word_emb,        // [VOCAB,H4]
    const float4* __restrict__ pos_emb,         // [MAX_POS,H4]
    const float4* __restrict__ tok_type_emb,    // [2,H4]
    const float4* __restrict__ match_emb,       // [11,H4]
    const float4* __restrict__ type_emb,        // [6,H4]
    const float4* __restrict__ ln_w,            // [H4]
    const float4* __restrict__ ln_b,            // [H4]
    float4*       __restrict__ out)             // [B,S,H4]
{
    const int tid  = threadIdx.x;
    const int warp = tid >> 5;
    const int lane = tid & 31;

    __shared__ float4 sgw[H4];
    __shared__ float4 sgb[H4];
    if (tid < H4) {
        sgw[tid] = ln_w[tid];
        sgb[tid] = ln_b[tid];
    }
    __syncthreads();

    // one warp owns 8 consecutive rows of one batch (8 | 512)
    const int gw_id = blockIdx.x * (TPB / 32) + warp;
    const int row0  = gw_id * RPW;
    const int b     = row0 >> 9;

    // per-warp batch metadata, one lane each (NC == 32), hoisted
    const int cp = col_pos[b * NC + lane];
    const int ci = col_idx[b * NC + lane];
    const int hl = header_len[b * NC + lane];

    #pragma unroll 1
    for (int r = 0; r < RPW; ++r) {
        const int row = row0 + r;
        const int s   = row & (SS - 1);

        // ---- column-scatter detection (register-only) ----
        const unsigned mmask = __ballot_sync(0xffffffffu, cp == s);
        int len = 0, cidx = 0;
        if (mmask) {
            const int c = __ffs(mmask) - 1;
            cidx = __shfl_sync(0xffffffffu, ci, c);
            len  = __shfl_sync(0xffffffffu, hl, cidx);
        }

        // ---- base vector: word embedding or pooled header ----
        float4 v[CPL];
        if (len > 0) {
            #pragma unroll
            for (int k = 0; k < CPL; ++k) v[k] = make_float4(0.f, 0.f, 0.f, 0.f);
            const int* hids = header_ids + (b * NC + cidx) * MHL;
            for (int l = 0; l < len; ++l) {
                const size_t base = (size_t)hids[l] * H4 + lane;
                #pragma unroll
                for (int k = 0; k < CPL; ++k) {
                    const float4 w = word_emb[base + k * 32];
                    v[k].x += w.x; v[k].y += w.y; v[k].z += w.z; v[k].w += w.w;
                }
            }
            const float inv = 1.0f / (float)len;
            #pragma unroll
            for (int k = 0; k < CPL; ++k) {
                v[k].x *= inv; v[k].y *= inv; v[k].z *= inv; v[k].w *= inv;
            }
        } else {
            const size_t base = (size_t)input_ids[row] * H4 + lane;
            #pragma unroll
            for (int k = 0; k < CPL; ++k) v[k] = word_emb[base + k * 32];
        }

        // ---- add positional + three small tables (L1-resident) ----
        const int tt = token_type_ids[row];
        const int mt = match_type_ids[row];
        const int ty = type_idx[row];

        const size_t pbase = (size_t)s  * H4 + lane;
        const size_t tbase = (size_t)tt * H4 + lane;
        const size_t mbase = (size_t)mt * H4 + lane;
        const size_t ybase = (size_t)ty * H4 + lane;
        #pragma unroll
        for (int k = 0; k < CPL; ++k) {
            const float4 pe = pos_emb[pbase + k * 32];
            const float4 te = tok_type_emb[tbase + k * 32];
            const float4 me = match_emb[mbase + k * 32];
            const float4 ye = type_emb[ybase + k * 32];
            v[k].x += pe.x + te.x + me.x + ye.x;
            v[k].y += pe.y + te.y + me.y + ye.y;
            v[k].z += pe.z + te.z + me.z + ye.z;
            v[k].w += pe.w + te.w + me.w + ye.w;
        }

        // ---- LayerNorm: warp-only butterfly reduce ----
        float sum = 0.f, sq = 0.f;
        #pragma unroll
        for (int k = 0; k < CPL; ++k) {
            sum += v[k].x + v[k].y + v[k].z + v[k].w;
            sq  += v[k].x * v[k].x + v[k].y * v[k].y
                 + v[k].z * v[k].z + v[k].w * v[k].w;
        }
        #pragma unroll
        for (int o = 16; o > 0; o >>= 1) {
            sum += __shfl_xor_sync(0xffffffffu, sum, o);
            sq  += __shfl_xor_sync(0xffffffffu, sq,  o);
        }
        const float mean = sum * (1.0f / HH);
        float var = fmaxf(sq * (1.0f / HH) - mean * mean, 0.0f);
        const float rstd = rsqrtf(var + 1e-12f);

        // ---- scale, shift, store ----
        float4* orow = out + (size_t)row * H4 + lane;
        #pragma unroll
        for (int k = 0; k < CPL; ++k) {
            const float4 gwv = sgw[lane + k * 32];
            const float4 gbv = sgb[lane + k * 32];
            float4 o;
            o.x = (v[k].x - mean) * rstd * gwv.x + gbv.x;
            o.y = (v[k].y - mean) * rstd * gwv.y + gbv.y;
            o.z = (v[k].z - mean) * rstd * gwv.z + gbv.z;
            o.w = (v[k].w - mean) * rstd * gwv.w + gbv.w;
            __stcs(orow + k * 32, o);
        }
    }
}

extern "C" void kernel_launch(void* const* d_in, const int* in_sizes, int n_in,
                              void* d_out, int out_size) {
    (void)in_sizes; (void)n_in; (void)out_size;
    const int*    input_ids       = (const int*)   d_in[0];
    const int*    header_ids      = (const int*)   d_in[1];
    const int*    token_type_ids  = (const int*)   d_in[2];
    const int*    match_type_ids  = (const int*)   d_in[3];
    const int*    type_idx        = (const int*)   d_in[4];
    const int*    col_pos         = (const int*)   d_in[5];
    const int*    col_idx         = (const int*)   d_in[6];
    const int*    header_len      = (const int*)   d_in[7];
    const float4* word_emb        = (const float4*)d_in[8];
    const float4* pos_emb         = (const float4*)d_in[9];
    const float4* tok_type_emb    = (const float4*)d_in[10];
    const float4* match_emb       = (const float4*)d_in[11];
    const float4* type_emb        = (const float4*)d_in[12];
    const float4* ln_w            = (const float4*)d_in[13];
    const float4* ln_b            = (const float4*)d_in[14];
    float4*       out             = (float4*)d_out;

    // single kernel: 16384 rows / (8 warps * 8 rows) = 256 CTAs
    const int grid = (BB * SS) / ((TPB / 32) * RPW);
    bert_emb_kernel<<<grid, TPB>>>(
        input_ids, header_ids, token_type_ids, match_type_ids, type_idx,
        col_pos, col_idx, header_len, word_emb, pos_emb,
        tok_type_emb, match_emb, type_emb, ln_w, ln_b, out);
}